// round 1
// baseline (speedup 1.0000x reference)
#include <cuda_runtime.h>

#define SEQ 512
#define BATCH 256
#define EMB 300
#define HID 10
#define G3 30

// Scratch: input-gate preactivations (allowed: static __device__ arrays)
__device__ float g_gif[BATCH * SEQ * G3];   // forward gi [B,S,3H]
__device__ float g_gib[BATCH * G3];         // backward gi at s=S-1 [B,3H]

// ---------- helpers ----------
__device__ __forceinline__ unsigned long long pk2(float lo, float hi) {
    unsigned long long r;
    asm("mov.b64 %0, {%1, %2};" : "=l"(r) : "f"(lo), "f"(hi));
    return r;
}
__device__ __forceinline__ void upk2(unsigned long long v, float& lo, float& hi) {
    asm("mov.b64 {%0, %1}, %2;" : "=f"(lo), "=f"(hi) : "l"(v));
}
__device__ __forceinline__ unsigned long long fma2(unsigned long long a,
                                                   unsigned long long b,
                                                   unsigned long long c) {
    unsigned long long d;
    asm("fma.rn.f32x2 %0, %1, %2, %3;" : "=l"(d) : "l"(a), "l"(b), "l"(c));
    return d;
}
__device__ __forceinline__ float sigf(float x) {
    return __fdividef(1.0f, 1.0f + __expf(-x));
}
__device__ __forceinline__ float tanhf2(float x) {
    // tanh(x) = 2*sigmoid(2x) - 1 ; safe at both tails (expf -> 0 or inf)
    return __fdividef(2.0f, 1.0f + __expf(-2.0f * x)) - 1.0f;
}

// ---------- K1: gi = x_row @ W_ih^T + b_ih, packed f32x2 ----------
// Weights staged in SMEM as 16 ull per k (15 gate-pairs + 1 zero pad),
// read as LDS.128; per k: 8 LDS.128 + 16 fma.f32x2.
#define STEPK(kk, v)                                                          \
    do {                                                                      \
        unsigned long long xx = pk2((v), (v));                                \
        const ulonglong2* wp = swv + (kk) * 8;                                \
        _Pragma("unroll")                                                     \
        for (int q = 0; q < 8; ++q) {                                         \
            ulonglong2 wq = wp[q];                                            \
            acc[2 * q]     = fma2(xx, wq.x, acc[2 * q]);                      \
            acc[2 * q + 1] = fma2(xx, wq.y, acc[2 * q + 1]);                  \
        }                                                                     \
    } while (0)

__global__ void __launch_bounds__(128) k_gi(
    const float* __restrict__ x, const float* __restrict__ w,
    const float* __restrict__ bias, float* __restrict__ out,
    int nrows, long xstride, long xoff)
{
    __shared__ ulonglong2 swv[EMB * 8];
    unsigned long long* sw = (unsigned long long*)swv;
    for (int i = threadIdx.x; i < EMB * 16; i += blockDim.x) {
        int k = i >> 4, p = i & 15;
        unsigned long long v = 0ULL;
        if (p < 15) v = pk2(w[(2 * p) * EMB + k], w[(2 * p + 1) * EMB + k]);
        sw[i] = v;
    }
    __syncthreads();

    int row = blockIdx.x * blockDim.x + threadIdx.x;
    if (row >= nrows) return;

    const float4* xr = (const float4*)(x + xoff + (long)row * xstride);
    unsigned long long acc[16];
#pragma unroll
    for (int p = 0; p < 16; ++p) acc[p] = 0ULL;

#pragma unroll 2
    for (int k4 = 0; k4 < EMB / 4; ++k4) {
        float4 xv = __ldg(xr + k4);
        STEPK(4 * k4 + 0, xv.x);
        STEPK(4 * k4 + 1, xv.y);
        STEPK(4 * k4 + 2, xv.z);
        STEPK(4 * k4 + 3, xv.w);
    }

    float* orow = out + (long)row * G3;
#pragma unroll
    for (int p = 0; p < 15; ++p) {
        float lo, hi;
        upk2(acc[p], lo, hi);
        orow[2 * p]     = lo + bias[2 * p];
        orow[2 * p + 1] = hi + bias[2 * p + 1];
    }
}

// ---------- K2: forward recurrence (1 warp = 1 batch row) + bwd step + head ----------
__global__ void __launch_bounds__(32) k_rec(
    const float* __restrict__ gif, const float* __restrict__ gib,
    const float* __restrict__ whh, const float* __restrict__ bhhf,
    const float* __restrict__ bhhb, const float* __restrict__ wlin,
    const float* __restrict__ blin, float* __restrict__ out)
{
    const int b = blockIdx.x;
    const int l = threadIdx.x;
    const int l30 = l < G3 ? l : 0;
    const unsigned m = 0xffffffffu;

    // lane l<30 owns gate row l of w_hh_f
    float wv[HID];
    float bias = 0.0f;
#pragma unroll
    for (int k = 0; k < HID; ++k) wv[k] = 0.0f;
    if (l < G3) {
#pragma unroll
        for (int k = 0; k < HID; ++k) wv[k] = whh[l * HID + k];
        bias = bhhf[l];
    }

    float h[HID];   // replicated across all lanes
#pragma unroll
    for (int k = 0; k < HID; ++k) h[k] = 0.0f;
    float hown = 0.0f;  // lane j<10 holds h[j]

    const float* gp = gif + (size_t)b * (SEQ * G3) + l30;
    float gcur = __ldg(gp);

    for (int t = 0; t < SEQ; ++t) {
        int tn = (t + 1 < SEQ) ? t + 1 : SEQ - 1;
        float gnext = __ldg(gp + tn * G3);  // prefetch next step

        // gh[l] = b_hh[l] + sum_k h[k] * w_hh[l][k]
        float a0 = bias, a1 = 0.0f;
#pragma unroll
        for (int k = 0; k < HID; k += 2) {
            a0 = fmaf(h[k],     wv[k],     a0);
            a1 = fmaf(h[k + 1], wv[k + 1], a1);
        }
        float gh = a0 + a1;
        float s  = gcur + gh;                    // i + gh (valid for r,z lanes)

        float az  = __shfl_sync(m, s,    l + 10);  // z preact for lane j<10
        float ghn = __shfl_sync(m, gh,   l + 20);  // recurrent n part
        float inn = __shfl_sync(m, gcur, l + 20);  // input n part

        float r = sigf(s);
        float z = sigf(az);
        float n = tanhf2(fmaf(r, ghn, inn));
        float hn = fmaf(z, hown - n, n);          // (1-z)*n + z*h

#pragma unroll
        for (int k = 0; k < HID; ++k) h[k] = __shfl_sync(m, hn, k);
        hown = hn;
        gcur = gnext;
    }

    // backward direction, single step from h0 = 0  (gh = b_hh_b)
    float gb = (l < G3) ? __ldg(gib + b * G3 + l) : 0.0f;
    float bb = (l < G3) ? bhhb[l] : 0.0f;
    float sb  = gb + bb;
    float azb = __shfl_sync(m, sb, l + 10);
    float gbn = __shfl_sync(m, gb, l + 20);
    float bbn = __shfl_sync(m, bb, l + 20);
    float rb = sigf(sb);
    float zb = sigf(azb);
    float nb = tanhf2(fmaf(rb, bbn, gbn));
    float hbv = (1.0f - zb) * nb;

    // linear head: out[b] = wlin[0:10]·hf + wlin[10:20]·hb + b_lin
    float c = 0.0f;
    if (l < HID) c = wlin[l] * hown + wlin[HID + l] * hbv;
    c += __shfl_down_sync(m, c, 8);
    c += __shfl_down_sync(m, c, 4);
    c += __shfl_down_sync(m, c, 2);
    c += __shfl_down_sync(m, c, 1);
    if (l == 0) out[b] = c + blin[0];
}

extern "C" void kernel_launch(void* const* d_in, const int* in_sizes, int n_in,
                              void* d_out, int out_size)
{
    const float* x      = (const float*)d_in[0];
    const float* w_ih_f = (const float*)d_in[1];
    const float* w_hh_f = (const float*)d_in[2];
    const float* b_ih_f = (const float*)d_in[3];
    const float* b_hh_f = (const float*)d_in[4];
    const float* w_ih_b = (const float*)d_in[5];
    /* w_hh_b (d_in[6]) is mathematically unused: h0 = 0 for the single bwd step */
    const float* b_ih_b = (const float*)d_in[7];
    const float* b_hh_b = (const float*)d_in[8];
    const float* w_lin  = (const float*)d_in[9];
    const float* b_lin  = (const float*)d_in[10];
    float* out = (float*)d_out;

    float *gif, *gib;
    cudaGetSymbolAddress((void**)&gif, g_gif);
    cudaGetSymbolAddress((void**)&gib, g_gib);

    const int rows = BATCH * SEQ;
    // forward gi for all (b,s)
    k_gi<<<(rows + 127) / 128, 128>>>(x, w_ih_f, b_ih_f, gif, rows, EMB, 0);
    // backward gi for s = S-1 only
    k_gi<<<(BATCH + 127) / 128, 128>>>(x, w_ih_b, b_ih_b, gib, BATCH,
                                       (long)SEQ * EMB, (long)(SEQ - 1) * EMB);
    // recurrence + backward step + head
    k_rec<<<BATCH, 32>>>(gif, gib, w_hh_f, b_hh_f, b_hh_b, w_lin, b_lin, out);
}

// round 2
// speedup vs baseline: 1.5870x; 1.5870x over previous
#include <cuda_runtime.h>

#define SEQ 512
#define BATCH 256
#define EMB 300
#define HID 10
#define G3 30

// Scratch (static __device__ arrays are allowed)
__device__ float g_gif[BATCH * G3 * SEQ];   // forward gi, TRANSPOSED: [B][3H][S]
__device__ float g_gib[BATCH * G3];         // backward gi at s=S-1: [B][3H]

// ---------- helpers ----------
__device__ __forceinline__ unsigned long long pk2(float lo, float hi) {
    unsigned long long r;
    asm("mov.b64 %0, {%1, %2};" : "=l"(r) : "f"(lo), "f"(hi));
    return r;
}
__device__ __forceinline__ void upk2(unsigned long long v, float& lo, float& hi) {
    asm("mov.b64 {%0, %1}, %2;" : "=f"(lo), "=f"(hi) : "l"(v));
}
__device__ __forceinline__ unsigned long long fma2(unsigned long long a,
                                                   unsigned long long b,
                                                   unsigned long long c) {
    unsigned long long d;
    asm("fma.rn.f32x2 %0, %1, %2, %3;" : "=l"(d) : "l"(a), "l"(b), "l"(c));
    return d;
}
__device__ __forceinline__ float tanha(float x) {
    float y;
    asm("tanh.approx.f32 %0, %1;" : "=f"(y) : "f"(x));
    return y;
}
__device__ __forceinline__ float sigf(float x) {
    return fmaf(tanha(0.5f * x), 0.5f, 0.5f);
}
__device__ __forceinline__ float getc(float4 v, int i) {
    return i == 0 ? v.x : i == 1 ? v.y : i == 2 ? v.z : v.w;
}

// ---------- K1: gi = x @ W_ih^T + b_ih, R=4 rows/thread, transposed output ----
// One block per batch element; thread t owns rows s = t, t+128, t+256, t+384.
__global__ void __launch_bounds__(128) k_gi4(
    const float* __restrict__ x, const float* __restrict__ w,
    const float* __restrict__ bias, float* __restrict__ out)
{
    __shared__ ulonglong2 swv[EMB * 8];
    unsigned long long* sw = (unsigned long long*)swv;
    for (int i = threadIdx.x; i < EMB * 16; i += blockDim.x) {
        int k = i >> 4, p = i & 15;
        unsigned long long v = 0ULL;
        if (p < 15) v = pk2(w[(2 * p) * EMB + k], w[(2 * p + 1) * EMB + k]);
        sw[i] = v;
    }
    __syncthreads();

    const int b   = blockIdx.x;
    const int tid = threadIdx.x;

    const float4* xr[4];
#pragma unroll
    for (int j = 0; j < 4; ++j)
        xr[j] = (const float4*)(x + ((size_t)b * SEQ + tid + 128 * j) * EMB);

    unsigned long long acc[4][15];
#pragma unroll
    for (int p = 0; p < 15; ++p) {
        unsigned long long bp = pk2(__ldg(bias + 2 * p), __ldg(bias + 2 * p + 1));
#pragma unroll
        for (int j = 0; j < 4; ++j) acc[j][p] = bp;
    }

    for (int k4 = 0; k4 < EMB / 4; ++k4) {
        float4 xv[4];
#pragma unroll
        for (int j = 0; j < 4; ++j) xv[j] = __ldg(xr[j] + k4);

#pragma unroll
        for (int kk = 0; kk < 4; ++kk) {
            const ulonglong2* wp = swv + (4 * k4 + kk) * 8;
            ulonglong2 wq[8];
#pragma unroll
            for (int q = 0; q < 8; ++q) wq[q] = wp[q];
#pragma unroll
            for (int j = 0; j < 4; ++j) {
                float xs = getc(xv[j], kk);
                unsigned long long xx = pk2(xs, xs);
#pragma unroll
                for (int q = 0; q < 7; ++q) {
                    acc[j][2 * q]     = fma2(xx, wq[q].x, acc[j][2 * q]);
                    acc[j][2 * q + 1] = fma2(xx, wq[q].y, acc[j][2 * q + 1]);
                }
                acc[j][14] = fma2(xx, wq[7].x, acc[j][14]);
            }
        }
    }

    float* ob = out + (size_t)b * (G3 * SEQ);
#pragma unroll
    for (int j = 0; j < 4; ++j) {
        int s = tid + 128 * j;
#pragma unroll
        for (int p = 0; p < 15; ++p) {
            float lo, hi;
            upk2(acc[j][p], lo, hi);
            ob[(2 * p) * SEQ + s]     = lo;
            ob[(2 * p + 1) * SEQ + s] = hi;
        }
    }
}

// ---------- K1b: backward gi (s = S-1 only), thread-per-row, normal layout ---
__global__ void __launch_bounds__(128) k_gib(
    const float* __restrict__ x, const float* __restrict__ w,
    const float* __restrict__ bias, float* __restrict__ out, int nrows)
{
    __shared__ ulonglong2 swv[EMB * 8];
    unsigned long long* sw = (unsigned long long*)swv;
    for (int i = threadIdx.x; i < EMB * 16; i += blockDim.x) {
        int k = i >> 4, p = i & 15;
        unsigned long long v = 0ULL;
        if (p < 15) v = pk2(w[(2 * p) * EMB + k], w[(2 * p + 1) * EMB + k]);
        sw[i] = v;
    }
    __syncthreads();

    int row = blockIdx.x * blockDim.x + threadIdx.x;
    if (row >= nrows) return;

    const float4* xr = (const float4*)(x + ((size_t)row * SEQ + SEQ - 1) * EMB);
    unsigned long long acc[15];
#pragma unroll
    for (int p = 0; p < 15; ++p)
        acc[p] = pk2(__ldg(bias + 2 * p), __ldg(bias + 2 * p + 1));

#pragma unroll 2
    for (int k4 = 0; k4 < EMB / 4; ++k4) {
        float4 xv = __ldg(xr + k4);
#pragma unroll
        for (int kk = 0; kk < 4; ++kk) {
            const ulonglong2* wp = swv + (4 * k4 + kk) * 8;
            float xs = getc(xv, kk);
            unsigned long long xx = pk2(xs, xs);
#pragma unroll
            for (int q = 0; q < 7; ++q) {
                ulonglong2 wq = wp[q];
                acc[2 * q]     = fma2(xx, wq.x, acc[2 * q]);
                acc[2 * q + 1] = fma2(xx, wq.y, acc[2 * q + 1]);
            }
            acc[14] = fma2(xx, wp[7].x, acc[14]);
        }
    }

    float* orow = out + (size_t)row * G3;
#pragma unroll
    for (int p = 0; p < 15; ++p) {
        float lo, hi;
        upk2(acc[p], lo, hi);
        orow[2 * p]     = lo;
        orow[2 * p + 1] = hi;
    }
}

// ---------- K2: forward recurrence (1 warp/batch) + bwd step + linear head ---
__global__ void __launch_bounds__(32) k_rec(
    const float* __restrict__ gif, const float* __restrict__ gib,
    const float* __restrict__ whh, const float* __restrict__ bhhf,
    const float* __restrict__ bhhb, const float* __restrict__ wlin,
    const float* __restrict__ blin, float* __restrict__ out)
{
    const int b = blockIdx.x;
    const int l = threadIdx.x;
    const int l30 = l < G3 ? l : 0;
    const unsigned m = 0xffffffffu;

    float wv[HID];
    float bias = 0.0f;
#pragma unroll
    for (int k = 0; k < HID; ++k) wv[k] = 0.0f;
    if (l < G3) {
#pragma unroll
        for (int k = 0; k < HID; ++k) wv[k] = whh[l * HID + k];
        bias = bhhf[l];
    }

    float h[HID];
#pragma unroll
    for (int k = 0; k < HID; ++k) h[k] = 0.0f;
    float hown = 0.0f;

    // transposed gi: lane reads consecutive timesteps; float4 = 4 steps
    const float4* gp = (const float4*)(gif + ((size_t)b * G3 + l30) * SEQ);
    float4 cur = __ldg(gp);

    for (int tb = 0; tb < SEQ / 4; ++tb) {
        float4 nxt = cur;
        if (tb + 1 < SEQ / 4) nxt = __ldg(gp + tb + 1);  // ~500cy ahead

#pragma unroll
        for (int u = 0; u < 4; ++u) {
            float gcur = getc(cur, u);
            float inn  = __shfl_sync(m, gcur, l + 20);   // off critical path

            // gh[l] = bias + h · w  (4 parallel chains)
            float a0 = bias, a1 = 0.0f, a2 = 0.0f, a3 = 0.0f;
            a0 = fmaf(h[0], wv[0], a0);  a1 = fmaf(h[1], wv[1], a1);
            a2 = fmaf(h[2], wv[2], a2);  a3 = fmaf(h[3], wv[3], a3);
            a0 = fmaf(h[4], wv[4], a0);  a1 = fmaf(h[5], wv[5], a1);
            a2 = fmaf(h[6], wv[6], a2);  a3 = fmaf(h[7], wv[7], a3);
            a0 = fmaf(h[8], wv[8], a0);  a1 = fmaf(h[9], wv[9], a1);
            float gh = (a0 + a1) + (a2 + a3);
            float s  = gcur + gh;

            float az  = __shfl_sync(m, s,  l + 10);
            float ghn = __shfl_sync(m, gh, l + 20);

            float r  = sigf(s);
            float z  = sigf(az);
            float n  = tanha(fmaf(r, ghn, inn));
            float hn = fmaf(z, hown - n, n);

#pragma unroll
            for (int k = 0; k < HID; ++k) h[k] = __shfl_sync(m, hn, k);
            hown = hn;
        }
        cur = nxt;
    }

    // backward direction: single step from h0 = 0 (gh = b_hh_b; w_hh_b unused)
    float gb = (l < G3) ? __ldg(gib + b * G3 + l) : 0.0f;
    float bb = (l < G3) ? bhhb[l] : 0.0f;
    float sb  = gb + bb;
    float azb = __shfl_sync(m, sb, l + 10);
    float gbn = __shfl_sync(m, gb, l + 20);
    float bbn = __shfl_sync(m, bb, l + 20);
    float rb  = sigf(sb);
    float zb  = sigf(azb);
    float nb  = tanha(fmaf(rb, bbn, gbn));
    float hbv = (1.0f - zb) * nb;

    float c = 0.0f;
    if (l < HID) c = wlin[l] * hown + wlin[HID + l] * hbv;
    c += __shfl_down_sync(m, c, 8);
    c += __shfl_down_sync(m, c, 4);
    c += __shfl_down_sync(m, c, 2);
    c += __shfl_down_sync(m, c, 1);
    if (l == 0) out[b] = c + blin[0];
}

extern "C" void kernel_launch(void* const* d_in, const int* in_sizes, int n_in,
                              void* d_out, int out_size)
{
    const float* x      = (const float*)d_in[0];
    const float* w_ih_f = (const float*)d_in[1];
    const float* w_hh_f = (const float*)d_in[2];
    const float* b_ih_f = (const float*)d_in[3];
    const float* b_hh_f = (const float*)d_in[4];
    const float* w_ih_b = (const float*)d_in[5];
    /* w_hh_b (d_in[6]) mathematically unused: h0 = 0 for the single bwd step */
    const float* b_ih_b = (const float*)d_in[7];
    const float* b_hh_b = (const float*)d_in[8];
    const float* w_lin  = (const float*)d_in[9];
    const float* b_lin  = (const float*)d_in[10];
    float* out = (float*)d_out;

    float *gif, *gib;
    cudaGetSymbolAddress((void**)&gif, g_gif);
    cudaGetSymbolAddress((void**)&gib, g_gib);

    // forward gi for all (b,s), transposed [B][3H][S]
    k_gi4<<<BATCH, 128>>>(x, w_ih_f, b_ih_f, gif);
    // backward gi for s = S-1 only
    k_gib<<<(BATCH + 127) / 128, 128>>>(x, w_ih_b, b_ih_b, gib, BATCH);
    // recurrence + backward step + head
    k_rec<<<BATCH, 32>>>(gif, gib, w_hh_f, b_hh_f, b_hh_b, w_lin, b_lin, out);
}

// round 3
// speedup vs baseline: 1.8684x; 1.1773x over previous
#include <cuda_runtime.h>

#define SEQ 512
#define BATCH 256
#define EMB 300
#define HID 10
#define G3 30
#define K4C (EMB / 4)   // 75

// Scratch (static __device__ arrays are allowed)
// forward gi, TRANSPOSED [B][3H][S]; gate rows 0..19 pre-scaled by 0.5
__device__ float g_gif[BATCH * G3 * SEQ];

// ---------- helpers ----------
__device__ __forceinline__ unsigned long long pk2(float lo, float hi) {
    unsigned long long r;
    asm("mov.b64 %0, {%1, %2};" : "=l"(r) : "f"(lo), "f"(hi));
    return r;
}
__device__ __forceinline__ void upk2(unsigned long long v, float& lo, float& hi) {
    asm("mov.b64 {%0, %1}, %2;" : "=f"(lo), "=f"(hi) : "l"(v));
}
__device__ __forceinline__ unsigned long long fma2(unsigned long long a,
                                                   unsigned long long b,
                                                   unsigned long long c) {
    unsigned long long d;
    asm("fma.rn.f32x2 %0, %1, %2, %3;" : "=l"(d) : "l"(a), "l"(b), "l"(c));
    return d;
}
__device__ __forceinline__ float tanha(float x) {
    float y;
    asm("tanh.approx.f32 %0, %1;" : "=f"(y) : "f"(x));
    return y;
}
__device__ __forceinline__ float sig_full(float x) {   // sigmoid from full preact
    return fmaf(tanha(0.5f * x), 0.5f, 0.5f);
}
__device__ __forceinline__ float getc(float4 v, int i) {
    return i == 0 ? v.x : i == 1 ? v.y : i == 2 ? v.z : v.w;
}

// ---------- K1: gi = x @ W_ih^T + b_ih (rows 0..19 pre-scaled by 0.5) ------
// Block = 256 rows, 128 threads. Thread = 8 rows (ro=tid>>2) x 4 gate-pairs
// (q=tid&3). Lane quads share x rows (LDG sector merge). Output transposed.
__global__ void __launch_bounds__(128, 4) k_gi(
    const float* __restrict__ x, const float* __restrict__ w,
    const float* __restrict__ bias, float* __restrict__ out)
{
    __shared__ ulonglong2 swv[EMB * 8];   // [k][8 x ulonglong2] = 16 gate-pairs
    unsigned long long* sw = (unsigned long long*)swv;
    for (int i = threadIdx.x; i < EMB * 16; i += 128) {
        int k = i >> 4, p = i & 15;
        unsigned long long v = 0ULL;
        if (p < 15) {
            float sc = (p < 10) ? 0.5f : 1.0f;   // fold sigmoid 1/2 into r,z rows
            v = pk2(sc * __ldg(w + (2 * p) * EMB + k),
                    sc * __ldg(w + (2 * p + 1) * EMB + k));
        }
        sw[i] = v;
    }
    __syncthreads();

    const int tid = threadIdx.x;
    const int ro  = tid >> 2;   // row-oct 0..31
    const int q   = tid & 3;    // gate quarter: pairs q*4 .. q*4+3
    const long row0 = (long)blockIdx.x * 256 + (long)ro * 8;

    const float4* xr = (const float4*)(x + row0 * EMB);

    unsigned long long acc[8][4];
#pragma unroll
    for (int p = 0; p < 4; ++p) {
        int P = q * 4 + p;
        unsigned long long bp = 0ULL;
        if (P < 15) {
            float sc = (P < 10) ? 0.5f : 1.0f;
            bp = pk2(sc * __ldg(bias + 2 * P), sc * __ldg(bias + 2 * P + 1));
        }
#pragma unroll
        for (int j = 0; j < 8; ++j) acc[j][p] = bp;
    }

    for (int k4 = 0; k4 < K4C; ++k4) {
        ulonglong2 wq[4][2];
#pragma unroll
        for (int kk = 0; kk < 4; ++kk) {
            wq[kk][0] = swv[(4 * k4 + kk) * 8 + q * 2];
            wq[kk][1] = swv[(4 * k4 + kk) * 8 + q * 2 + 1];
        }
#pragma unroll
        for (int half = 0; half < 2; ++half) {
            float4 xv[4];
#pragma unroll
            for (int j = 0; j < 4; ++j)
                xv[j] = __ldg(xr + (half * 4 + j) * K4C + k4);
#pragma unroll
            for (int kk = 0; kk < 4; ++kk) {
#pragma unroll
                for (int j = 0; j < 4; ++j) {
                    float xs = getc(xv[j], kk);
                    unsigned long long xx = pk2(xs, xs);
                    int jj = half * 4 + j;
                    acc[jj][0] = fma2(xx, wq[kk][0].x, acc[jj][0]);
                    acc[jj][1] = fma2(xx, wq[kk][0].y, acc[jj][1]);
                    acc[jj][2] = fma2(xx, wq[kk][1].x, acc[jj][2]);
                    acc[jj][3] = fma2(xx, wq[kk][1].y, acc[jj][3]);
                }
            }
        }
    }

    const long b  = row0 >> 9;          // / SEQ
    const int  s0 = (int)(row0 & 511);  // % SEQ
    float* ob = out + b * (long)(G3 * SEQ) + s0;
#pragma unroll
    for (int p = 0; p < 4; ++p) {
        int P = q * 4 + p;
        if (P < 15) {
#pragma unroll
            for (int half = 0; half < 2; ++half) {
                float l0, h0, l1, h1, l2, h2, l3, h3;
                upk2(acc[half * 4 + 0][p], l0, h0);
                upk2(acc[half * 4 + 1][p], l1, h1);
                upk2(acc[half * 4 + 2][p], l2, h2);
                upk2(acc[half * 4 + 3][p], l3, h3);
                *(float4*)(ob + (2 * P) * SEQ + half * 4)     = make_float4(l0, l1, l2, l3);
                *(float4*)(ob + (2 * P + 1) * SEQ + half * 4) = make_float4(h0, h1, h2, h3);
            }
        }
    }
}

// ---------- K2: fwd recurrence (1 warp/batch) + fused bwd gi/step + head ----
__global__ void __launch_bounds__(32) k_rec(
    const float* __restrict__ gif, const float* __restrict__ x,
    const float* __restrict__ w_ihb, const float* __restrict__ b_ihb,
    const float* __restrict__ whh, const float* __restrict__ bhhf,
    const float* __restrict__ bhhb, const float* __restrict__ wlin,
    const float* __restrict__ blin, float* __restrict__ out)
{
    const int b = blockIdx.x;
    const int l = threadIdx.x;
    const int l30 = l < G3 ? l : 0;
    const unsigned m = 0xffffffffu;
    const float scl = (l < 20) ? 0.5f : 1.0f;   // fold sigmoid 1/2 into r,z rows

    // ---- fused backward-direction gi at s = S-1 (one-time) ----
    float gb;
    {
        const float4* xq = (const float4*)(x + ((size_t)b * SEQ + SEQ - 1) * EMB);
        const float4* wq = (const float4*)(w_ihb + (size_t)l30 * EMB);
        float a0 = 0, a1 = 0, a2 = 0, a3 = 0;
#pragma unroll 5
        for (int k4 = 0; k4 < K4C; ++k4) {
            float4 xv = __ldg(xq + k4);
            float4 wv4 = __ldg(wq + k4);
            a0 = fmaf(xv.x, wv4.x, a0);
            a1 = fmaf(xv.y, wv4.y, a1);
            a2 = fmaf(xv.z, wv4.z, a2);
            a3 = fmaf(xv.w, wv4.w, a3);
        }
        gb = (a0 + a1) + (a2 + a3) + ((l < G3) ? __ldg(b_ihb + l) : 0.0f);
    }

    // ---- forward recurrence setup (w_hh/b_hh rows 0..19 scaled by 0.5) ----
    float wv[HID];
    float bias = 0.0f;
#pragma unroll
    for (int k = 0; k < HID; ++k) wv[k] = 0.0f;
    if (l < G3) {
#pragma unroll
        for (int k = 0; k < HID; ++k) wv[k] = scl * whh[l * HID + k];
        bias = scl * bhhf[l];
    }

    float h[HID];
#pragma unroll
    for (int k = 0; k < HID; ++k) h[k] = 0.0f;
    float hown = 0.0f;

    const float4* gp = (const float4*)(gif + ((size_t)b * G3 + l30) * SEQ);
    float4 cur = __ldg(gp);

    for (int tb = 0; tb < SEQ / 4; ++tb) {
        float4 nxt = cur;
        if (tb + 1 < SEQ / 4) nxt = __ldg(gp + tb + 1);

#pragma unroll
        for (int u = 0; u < 4; ++u) {
            float gcur = getc(cur, u);
            float inn  = __shfl_sync(m, gcur, l + 20);

            float a0 = bias, a1 = 0.0f, a2 = 0.0f, a3 = 0.0f;
            a0 = fmaf(h[0], wv[0], a0);  a1 = fmaf(h[1], wv[1], a1);
            a2 = fmaf(h[2], wv[2], a2);  a3 = fmaf(h[3], wv[3], a3);
            a0 = fmaf(h[4], wv[4], a0);  a1 = fmaf(h[5], wv[5], a1);
            a2 = fmaf(h[6], wv[6], a2);  a3 = fmaf(h[7], wv[7], a3);
            a0 = fmaf(h[8], wv[8], a0);  a1 = fmaf(h[9], wv[9], a1);
            float gh = (a0 + a1) + (a2 + a3);   // half-preact for l<20, full for n
            float s  = gcur + gh;

            float t   = tanha(s);               // all lanes; tanh(pre/2) on r,z
            float ghn = __shfl_sync(m, gh, l + 20);
            float tz  = __shfl_sync(m, t,  l + 10);

            float r  = fmaf(t,  0.5f, 0.5f);
            float z  = fmaf(tz, 0.5f, 0.5f);
            float n  = tanha(fmaf(r, ghn, inn));
            float hn = fmaf(z, hown - n, n);

#pragma unroll
            for (int k = 0; k < HID; ++k) h[k] = __shfl_sync(m, hn, k);
            hown = hn;
        }
        cur = nxt;
    }

    // ---- backward direction: single step from h0 = 0 (gh = b_hh_b) ----
    float bb  = (l < G3) ? __ldg(bhhb + l) : 0.0f;
    float sb  = gb + bb;
    float azb = __shfl_sync(m, sb, l + 10);
    float gbn = __shfl_sync(m, gb, l + 20);
    float bbn = __shfl_sync(m, bb, l + 20);
    float rb  = sig_full(sb);
    float zb  = sig_full(azb);
    float nb  = tanha(fmaf(rb, bbn, gbn));
    float hbv = (1.0f - zb) * nb;

    // ---- linear head ----
    float c = 0.0f;
    if (l < HID) c = wlin[l] * hown + wlin[HID + l] * hbv;
    c += __shfl_down_sync(m, c, 8);
    c += __shfl_down_sync(m, c, 4);
    c += __shfl_down_sync(m, c, 2);
    c += __shfl_down_sync(m, c, 1);
    if (l == 0) out[b] = c + blin[0];
}

extern "C" void kernel_launch(void* const* d_in, const int* in_sizes, int n_in,
                              void* d_out, int out_size)
{
    const float* x      = (const float*)d_in[0];
    const float* w_ih_f = (const float*)d_in[1];
    const float* w_hh_f = (const float*)d_in[2];
    const float* b_ih_f = (const float*)d_in[3];
    const float* b_hh_f = (const float*)d_in[4];
    const float* w_ih_b = (const float*)d_in[5];
    /* w_hh_b (d_in[6]) mathematically unused: h0 = 0 for the single bwd step */
    const float* b_ih_b = (const float*)d_in[7];
    const float* b_hh_b = (const float*)d_in[8];
    const float* w_lin  = (const float*)d_in[9];
    const float* b_lin  = (const float*)d_in[10];
    float* out = (float*)d_out;

    float* gif;
    cudaGetSymbolAddress((void**)&gif, g_gif);

    k_gi<<<(BATCH * SEQ) / 256, 128>>>(x, w_ih_f, b_ih_f, gif);
    k_rec<<<BATCH, 32>>>(gif, x, w_ih_b, b_ih_b, w_hh_f, b_hh_f, b_hh_b,
                         w_lin, b_lin, out);
}